// round 7
// baseline (speedup 1.0000x reference)
#include <cuda_runtime.h>

#define NV 8192
#define NC 4096
#define NB 512
#define NE 24576
#define NITER 5
#define EPSF 1e-12f
// clip = float(1 - 1e-7) = 1 - 2^-23.  Image of [-clip, clip] under (1+x)/(1-x):
#define RMAXF 16777215.0f      // = 2^24 - 1
#define RMINF 5.9604648e-8f    // = 1/(2^24 - 1) rounded

// Persistent scratch (device globals: allocation-free per harness rules)
__device__ float  g_st[NE * NB];   // signed (|tanh(msg/2)|+eps), edge-major [E,B]  ~50 MB
__device__ float  g_P[NC * NB];    // per-check signed product of 6 st's [C,B]       ~8 MB
__device__ float2 g_LE[NV * NB];   // {llr, exp(llr)} transposed [N,B]              ~32 MB
__device__ int    g_inv[NE];       // check -> 6 edge ids (atomic order; sorted in regs by consumers)
__device__ int    g_cnt[NC];       // build counters

// ---------------------------------------------------------------- prep: transpose llr, exp(llr), zero counters
__global__ void k_prep(const float* __restrict__ llr) {
    __shared__ float tile[32][33];
    int tx = threadIdx.x, ty = threadIdx.y;        // block (32,8)
    int vt = blockIdx.x * 32;                      // grid.x = NV/32 = 256
    int bt = blockIdx.y * 32;                      // grid.y = NB/32 = 16
#pragma unroll
    for (int i = 0; i < 4; i++)
        tile[ty + i * 8][tx] = llr[(bt + ty + i * 8) * NV + vt + tx];

    int gtid = (blockIdx.y * gridDim.x + blockIdx.x) * 256 + ty * 32 + tx;
    if (gtid < NC) g_cnt[gtid] = 0;

    __syncthreads();
#pragma unroll
    for (int i = 0; i < 4; i++) {
        int v = vt + ty + i * 8;
        int b = bt + tx;
        float l = tile[tx][ty + i * 8];
        g_LE[v * NB + b] = make_float2(l, __expf(l));
    }
}

// ---------------------------------------------------------------- inverse map (check -> edges)
__global__ void build_inv(const int* __restrict__ chk) {
    int e = blockIdx.x * blockDim.x + threadIdx.x;
    if (e < NE) {
        int c = chk[e];
        int s = atomicAdd(&g_cnt[c], 1);
        g_inv[c * 6 + s] = e;
    }
}

// ---------------------------------------------------------------- helpers
__device__ __forceinline__ float tanh_half_from_exp(float el) {
    float t = __fdividef(el - 1.0f, el + 1.0f);
    return t + copysignf(EPSF, t);
}

__device__ __forceinline__ float clamp_r(float r) {
    return fminf(fmaxf(r, RMINF), RMAXF);
}

// ---------------------------------------------------------------- check product (8 floats / thread)
__global__ void c_kernel(int first) {
    int tx = threadIdx.x, ty = threadIdx.y;        // block (32,8)
    int b  = (blockIdx.x * 32 + tx) * 8;           // grid.x = 2  (64 batch-octets)
    int c  = blockIdx.y * 8 + ty;                  // grid.y = NC/8 = 512

    int idx[6];
#pragma unroll
    for (int k = 0; k < 6; k++) idx[k] = g_inv[c * 6 + k];
    // register insertion sort (ascending edge id) every call — no shared-state mutation
#pragma unroll
    for (int i = 1; i < 6; i++)
#pragma unroll
        for (int j = i; j > 0; j--)
            if (idx[j] < idx[j - 1]) { int t = idx[j]; idx[j] = idx[j - 1]; idx[j - 1] = t; }

    float p[8];
    if (first) {
        // iter-0 st depends only on the variable: recompute from cached e^llr
#pragma unroll
        for (int j = 0; j < 8; j++) p[j] = 1.0f;
#pragma unroll
        for (int k = 0; k < 6; k++) {
            int v = idx[k] / 3;
            const float4* le = (const float4*)&g_LE[v * NB + b];  // 8 float2 = 4 float4
#pragma unroll
            for (int q = 0; q < 4; q++) {
                float4 a = le[q];
                p[2 * q + 0] *= tanh_half_from_exp(a.y);
                p[2 * q + 1] *= tanh_half_from_exp(a.w);
            }
        }
    } else {
#pragma unroll
        for (int j = 0; j < 8; j++) p[j] = 1.0f;
#pragma unroll
        for (int k = 0; k < 6; k++) {
            float4 s0 = *(const float4*)&g_st[idx[k] * NB + b];
            float4 s1 = *(const float4*)&g_st[idx[k] * NB + b + 4];
            p[0] *= s0.x; p[1] *= s0.y; p[2] *= s0.z; p[3] *= s0.w;
            p[4] *= s1.x; p[5] *= s1.y; p[6] *= s1.z; p[7] *= s1.w;
        }
    }
    *(float4*)&g_P[c * NB + b]     = make_float4(p[0], p[1], p[2], p[3]);
    *(float4*)&g_P[c * NB + b + 4] = make_float4(p[4], p[5], p[6], p[7]);
}

// ---------------------------------------------------------------- fused check-update(i) + var-update(i+1) + output(i)
// 4-wide over batch: all global accesses are .128, index math amortized 4x.
__global__ void v_kernel(const int* __restrict__ chk, float* __restrict__ out,
                         int iter, int first, int update) {
    __shared__ float tile[32][129];                // 32 v rows x 128 b cols (pad -> conflict-free col reads)
    int tx = threadIdx.x, ty = threadIdx.y;        // block (32,8)
    int b4 = blockIdx.x * 128 + tx * 4;            // grid.x = NB/128 = 4
    int v0 = blockIdx.y * 32;                      // grid.y = NV/32 = 256

#pragma unroll
    for (int s = 0; s < 4; s++) {
        int vl = s * 8 + ty;
        int v  = v0 + vl;
        int e0 = 3 * v;

        float4 le0 = *(const float4*)&g_LE[v * NB + b4];       // b4, b4+1
        float4 le1 = *(const float4*)&g_LE[v * NB + b4 + 2];   // b4+2, b4+3
        float l[4]  = {le0.x, le0.z, le1.x, le1.z};
        float EL[4] = {le0.y, le0.w, le1.y, le1.w};

        float st[3][4];
        if (first) {
#pragma unroll
            for (int j = 0; j < 4; j++) {
                float t = tanh_half_from_exp(EL[j]);   // all 3 edges identical at iter 0
                st[0][j] = t; st[1][j] = t; st[2][j] = t;
            }
        } else {
#pragma unroll
            for (int k = 0; k < 3; k++) {
                float4 sv = *(const float4*)&g_st[(e0 + k) * NB + b4];
                st[k][0] = sv.x; st[k][1] = sv.y; st[k][2] = sv.z; st[k][3] = sv.w;
            }
        }

        int c0 = chk[e0 + 0], c1 = chk[e0 + 1], c2 = chk[e0 + 2];  // uniform per warp
        float4 pv0 = *(const float4*)&g_P[c0 * NB + b4];
        float4 pv1 = *(const float4*)&g_P[c1 * NB + b4];
        float4 pv2 = *(const float4*)&g_P[c2 * NB + b4];
        float p[3][4] = {{pv0.x, pv0.y, pv0.z, pv0.w},
                         {pv1.x, pv1.y, pv1.z, pv1.w},
                         {pv2.x, pv2.y, pv2.z, pv2.w}};

        float w[3][4];
#pragma unroll
        for (int j = 0; j < 4; j++) {
            // r_e = e^{ext_e} = (st+P)/(st-P); signs cancel, r >= 0.
            float r0 = clamp_r(__fdividef(st[0][j] + p[0][j], st[0][j] - p[0][j]));
            float r1 = clamp_r(__fdividef(st[1][j] + p[1][j], st[1][j] - p[1][j]));
            float r2 = clamp_r(__fdividef(st[2][j] + p[2][j], st[2][j] - p[2][j]));
            float r12 = r1 * r2;
            tile[vl][tx * 4 + j] = l[j] + __logf(r0 * r12);   // out = llr + sum ext
            if (update) {
                // e^{msg_e} = e^llr * product of the OTHER two r's
                w[0][j] = tanh_half_from_exp(EL[j] * r12);
                w[1][j] = tanh_half_from_exp(EL[j] * (r0 * r2));
                w[2][j] = tanh_half_from_exp(EL[j] * (r0 * r1));
            }
        }
        if (update) {
#pragma unroll
            for (int k = 0; k < 3; k++)
                *(float4*)&g_st[(e0 + k) * NB + b4] =
                    make_float4(w[k][0], w[k][1], w[k][2], w[k][3]);
        }
    }
    __syncthreads();

    // coalesced transposed write: out[iter][b][v], 128B per warp-row
    int base = iter * (NB * NV) + v0 + tx;
#pragma unroll 4
    for (int r = ty; r < 128; r += 8) {
        int b = blockIdx.x * 128 + r;
        out[base + b * NV] = tile[tx][r];
    }
}

// ---------------------------------------------------------------- launch
extern "C" void kernel_launch(void* const* d_in, const int* in_sizes, int n_in,
                              void* d_out, int out_size) {
    const float* llr = (const float*)d_in[0];
    // d_in[1] = var_index: structured as repeat(arange(NV), 3) -> not needed
    const int* chk = (const int*)d_in[2];
    float* out = (float*)d_out;

    dim3 blk(32, 8);
    k_prep<<<dim3(NV / 32, NB / 32), blk>>>(llr);
    build_inv<<<(NE + 255) / 256, 256>>>(chk);

    for (int i = 0; i < NITER; i++) {
        c_kernel<<<dim3(2, NC / 8), blk>>>(i == 0);
        v_kernel<<<dim3(NB / 128, NV / 32), blk>>>(chk, out, i, i == 0, (i < NITER - 1) ? 1 : 0);
    }
}

// round 8
// speedup vs baseline: 1.1521x; 1.1521x over previous
#include <cuda_runtime.h>

#define NV 8192
#define NC 4096
#define NB 512
#define NE 24576
#define NITER 5
#define EPSF 1e-12f
// clip = float(1 - 1e-7) = 1 - 2^-23.  Image of [-clip, clip] under (1+x)/(1-x):
#define RMAXF 16777215.0f      // = 2^24 - 1
#define RMINF 5.9604648e-8f    // = 1/(2^24 - 1) rounded

// Persistent scratch (device globals: allocation-free per harness rules)
__device__ float g_st[NE * NB];    // signed (|tanh(msg/2)|+eps), edge-major [E,B]  ~50 MB
__device__ float g_P[NC * NB];     // per-check signed product of 6 st's [C,B]       ~8 MB
__device__ float g_llrT[NV * NB];  // llr transposed [N,B]                          ~16 MB
__device__ float g_EL[NV * NB];    // exp(llr) transposed [N,B]                     ~16 MB
__device__ int   g_inv[NE];        // check -> 6 edge ids (atomic order; reg-sorted by consumers)
__device__ int   g_cnt[NC];        // build counters

// ---------------------------------------------------------------- prep: transpose llr, exp(llr), zero counters
__global__ void k_prep(const float* __restrict__ llr) {
    __shared__ float tile[32][33];
    int tx = threadIdx.x, ty = threadIdx.y;        // block (32,8)
    int vt = blockIdx.x * 32;                      // grid.x = NV/32 = 256
    int bt = blockIdx.y * 32;                      // grid.y = NB/32 = 16
#pragma unroll
    for (int i = 0; i < 4; i++)
        tile[ty + i * 8][tx] = llr[(bt + ty + i * 8) * NV + vt + tx];

    int gtid = (blockIdx.y * gridDim.x + blockIdx.x) * 256 + ty * 32 + tx;
    if (gtid < NC) g_cnt[gtid] = 0;

    __syncthreads();
#pragma unroll
    for (int i = 0; i < 4; i++) {
        int v = vt + ty + i * 8;
        int b = bt + tx;
        float l = tile[tx][ty + i * 8];
        g_llrT[v * NB + b] = l;
        g_EL[v * NB + b]   = __expf(l);
    }
}

// ---------------------------------------------------------------- inverse map (check -> edges)
__global__ void build_inv(const int* __restrict__ chk) {
    int e = blockIdx.x * blockDim.x + threadIdx.x;
    if (e < NE) {
        int c = chk[e];
        int s = atomicAdd(&g_cnt[c], 1);
        g_inv[c * 6 + s] = e;
    }
}

// ---------------------------------------------------------------- helpers
__device__ __forceinline__ float tanh_half_from_exp(float el) {
    float t = __fdividef(el - 1.0f, el + 1.0f);
    return t + copysignf(EPSF, t);
}

__device__ __forceinline__ float clamp_r(float r) {
    return fminf(fmaxf(r, RMINF), RMAXF);
}

// ---------------------------------------------------------------- check product (4 floats / thread, contiguous)
__global__ void c_kernel(int first) {
    int tx = threadIdx.x, ty = threadIdx.y;        // block (32,8)
    int b  = (blockIdx.x * 32 + tx) * 4;           // grid.x = 4  (128 batch-quads)
    int c  = blockIdx.y * 8 + ty;                  // grid.y = NC/8 = 512

    int idx[6];
#pragma unroll
    for (int k = 0; k < 6; k++) idx[k] = g_inv[c * 6 + k];
    // register insertion sort (ascending edge id) every call — deterministic product
    // order matching segment_sum; no shared-state mutation.
#pragma unroll
    for (int i = 1; i < 6; i++)
#pragma unroll
        for (int j = i; j > 0; j--)
            if (idx[j] < idx[j - 1]) { int t = idx[j]; idx[j] = idx[j - 1]; idx[j - 1] = t; }

    float4 p = make_float4(1.f, 1.f, 1.f, 1.f);
    if (first) {
        // iter-0 st depends only on the variable: recompute from cached e^llr (planar, full-width loads)
#pragma unroll
        for (int k = 0; k < 6; k++) {
            int v = idx[k] / 3;
            float4 e = *(const float4*)&g_EL[v * NB + b];
            p.x *= tanh_half_from_exp(e.x);
            p.y *= tanh_half_from_exp(e.y);
            p.z *= tanh_half_from_exp(e.z);
            p.w *= tanh_half_from_exp(e.w);
        }
    } else {
#pragma unroll
        for (int k = 0; k < 6; k++) {
            float4 s = *(const float4*)&g_st[idx[k] * NB + b];
            p.x *= s.x; p.y *= s.y; p.z *= s.z; p.w *= s.w;
        }
    }
    *(float4*)&g_P[c * NB + b] = p;
}

// ---------------------------------------------------------------- fused check-update(i) + var-update(i+1) + output(i)
// 4-wide over batch: all global accesses .128; launch_bounds caps regs for occupancy.
__global__ void __launch_bounds__(256, 6)
v_kernel(const int* __restrict__ chk, float* __restrict__ out,
         int iter, int first, int update) {
    __shared__ float tile[32][129];                // 32 v rows x 128 b cols (pad -> conflict-free col reads)
    int tx = threadIdx.x, ty = threadIdx.y;        // block (32,8)
    int b4 = blockIdx.x * 128 + tx * 4;            // grid.x = NB/128 = 4
    int v0 = blockIdx.y * 32;                      // grid.y = NV/32 = 256

#pragma unroll
    for (int s = 0; s < 4; s++) {
        int vl = s * 8 + ty;
        int v  = v0 + vl;
        int e0 = 3 * v;

        float4 lv = *(const float4*)&g_llrT[v * NB + b4];
        float4 Ev = *(const float4*)&g_EL[v * NB + b4];
        float l[4]  = {lv.x, lv.y, lv.z, lv.w};
        float EL[4] = {Ev.x, Ev.y, Ev.z, Ev.w};

        float st[3][4];
        if (first) {
#pragma unroll
            for (int j = 0; j < 4; j++) {
                float t = tanh_half_from_exp(EL[j]);   // all 3 edges identical at iter 0
                st[0][j] = t; st[1][j] = t; st[2][j] = t;
            }
        } else {
#pragma unroll
            for (int k = 0; k < 3; k++) {
                float4 sv = *(const float4*)&g_st[(e0 + k) * NB + b4];
                st[k][0] = sv.x; st[k][1] = sv.y; st[k][2] = sv.z; st[k][3] = sv.w;
            }
        }

        int c0 = chk[e0 + 0], c1 = chk[e0 + 1], c2 = chk[e0 + 2];  // uniform per warp
        float4 pv0 = *(const float4*)&g_P[c0 * NB + b4];
        float4 pv1 = *(const float4*)&g_P[c1 * NB + b4];
        float4 pv2 = *(const float4*)&g_P[c2 * NB + b4];
        float p[3][4] = {{pv0.x, pv0.y, pv0.z, pv0.w},
                         {pv1.x, pv1.y, pv1.z, pv1.w},
                         {pv2.x, pv2.y, pv2.z, pv2.w}};

        float w[3][4];
#pragma unroll
        for (int j = 0; j < 4; j++) {
            // r_e = e^{ext_e} = (st+P)/(st-P); signs cancel, r >= 0.
            float r0 = clamp_r(__fdividef(st[0][j] + p[0][j], st[0][j] - p[0][j]));
            float r1 = clamp_r(__fdividef(st[1][j] + p[1][j], st[1][j] - p[1][j]));
            float r2 = clamp_r(__fdividef(st[2][j] + p[2][j], st[2][j] - p[2][j]));
            float r12 = r1 * r2;
            tile[vl][tx * 4 + j] = l[j] + __logf(r0 * r12);   // out = llr + sum ext
            if (update) {
                // e^{msg_e} = e^llr * product of the OTHER two r's (no exp/log round-trip)
                w[0][j] = tanh_half_from_exp(EL[j] * r12);
                w[1][j] = tanh_half_from_exp(EL[j] * (r0 * r2));
                w[2][j] = tanh_half_from_exp(EL[j] * (r0 * r1));
            }
        }
        if (update) {
#pragma unroll
            for (int k = 0; k < 3; k++)
                *(float4*)&g_st[(e0 + k) * NB + b4] =
                    make_float4(w[k][0], w[k][1], w[k][2], w[k][3]);
        }
    }
    __syncthreads();

    // coalesced transposed write: out[iter][b][v], 128B per warp-row
    int base = iter * (NB * NV) + v0 + tx;
#pragma unroll 4
    for (int r = ty; r < 128; r += 8) {
        int b = blockIdx.x * 128 + r;
        out[base + b * NV] = tile[tx][r];
    }
}

// ---------------------------------------------------------------- launch
extern "C" void kernel_launch(void* const* d_in, const int* in_sizes, int n_in,
                              void* d_out, int out_size) {
    const float* llr = (const float*)d_in[0];
    // d_in[1] = var_index: structured as repeat(arange(NV), 3) -> not needed
    const int* chk = (const int*)d_in[2];
    float* out = (float*)d_out;

    dim3 blk(32, 8);
    k_prep<<<dim3(NV / 32, NB / 32), blk>>>(llr);
    build_inv<<<(NE + 255) / 256, 256>>>(chk);

    for (int i = 0; i < NITER; i++) {
        c_kernel<<<dim3(4, NC / 8), blk>>>(i == 0);
        v_kernel<<<dim3(NB / 128, NV / 32), blk>>>(chk, out, i, i == 0, (i < NITER - 1) ? 1 : 0);
    }
}

// round 9
// speedup vs baseline: 1.2290x; 1.0668x over previous
#include <cuda_runtime.h>

#define NV 8192
#define NC 4096
#define NB 512
#define NE 24576
#define NITER 5
#define EPSF 1e-12f
// clip = float(1 - 1e-7) = 1 - 2^-23.  Image of [-clip, clip] under (1+x)/(1-x):
#define RMAXF 16777215.0f      // = 2^24 - 1
#define RMINF 5.9604648e-8f    // = 1/(2^24 - 1) rounded

// Persistent scratch (device globals: allocation-free per harness rules)
__device__ float g_st[NE * NB];    // signed (|tanh(msg/2)|+eps), edge-major [E,B]  ~50 MB
__device__ float g_P[NC * NB];     // per-check signed product of 6 st's [C,B]       ~8 MB
__device__ float g_llrT[NV * NB];  // llr transposed [N,B]                          ~16 MB
__device__ float g_EL[NV * NB];    // exp(llr) transposed [N,B]                     ~16 MB
__device__ int   g_inv[NE];        // check -> 6 edge ids (atomic order; reg-sorted by consumers)
__device__ int   g_cnt[NC];        // build counters

// ---------------------------------------------------------------- prep: transpose llr, exp(llr), zero counters
__global__ void k_prep(const float* __restrict__ llr) {
    __shared__ float tile[32][33];
    int tx = threadIdx.x, ty = threadIdx.y;        // block (32,8)
    int vt = blockIdx.x * 32;                      // grid.x = NV/32 = 256
    int bt = blockIdx.y * 32;                      // grid.y = NB/32 = 16
#pragma unroll
    for (int i = 0; i < 4; i++)
        tile[ty + i * 8][tx] = llr[(bt + ty + i * 8) * NV + vt + tx];

    int gtid = (blockIdx.y * gridDim.x + blockIdx.x) * 256 + ty * 32 + tx;
    if (gtid < NC) g_cnt[gtid] = 0;

    __syncthreads();
#pragma unroll
    for (int i = 0; i < 4; i++) {
        int v = vt + ty + i * 8;
        int b = bt + tx;
        float l = tile[tx][ty + i * 8];
        g_llrT[v * NB + b] = l;
        g_EL[v * NB + b]   = __expf(l);
    }
}

// ---------------------------------------------------------------- inverse map (check -> edges)
__global__ void build_inv(const int* __restrict__ chk) {
    int e = blockIdx.x * blockDim.x + threadIdx.x;
    if (e < NE) {
        int c = chk[e];
        int s = atomicAdd(&g_cnt[c], 1);
        g_inv[c * 6 + s] = e;
    }
}

// ---------------------------------------------------------------- helpers
__device__ __forceinline__ float tanh_half_from_exp(float el) {
    float t = __fdividef(el - 1.0f, el + 1.0f);
    return t + copysignf(EPSF, t);
}

__device__ __forceinline__ float clamp_r(float r) {
    return fminf(fmaxf(r, RMINF), RMAXF);
}

// ---------------------------------------------------------------- check product (4 floats / thread, contiguous)
template <int FIRST>
__global__ void c_kernel() {
    int tx = threadIdx.x, ty = threadIdx.y;        // block (32,8)
    int b  = (blockIdx.x * 32 + tx) * 4;           // grid.x = 4  (128 batch-quads)
    int c  = blockIdx.y * 8 + ty;                  // grid.y = NC/8 = 512

    int idx[6];
#pragma unroll
    for (int k = 0; k < 6; k++) idx[k] = g_inv[c * 6 + k];
    // register insertion sort (ascending edge id) every call — deterministic product
    // order matching segment_sum; no shared-state mutation.
#pragma unroll
    for (int i = 1; i < 6; i++)
#pragma unroll
        for (int j = i; j > 0; j--)
            if (idx[j] < idx[j - 1]) { int t = idx[j]; idx[j] = idx[j - 1]; idx[j - 1] = t; }

    float4 p = make_float4(1.f, 1.f, 1.f, 1.f);
    if (FIRST) {
        // iter-0 st depends only on the variable: recompute from cached e^llr
#pragma unroll
        for (int k = 0; k < 6; k++) {
            int v = idx[k] / 3;
            float4 e = *(const float4*)&g_EL[v * NB + b];
            p.x *= tanh_half_from_exp(e.x);
            p.y *= tanh_half_from_exp(e.y);
            p.z *= tanh_half_from_exp(e.z);
            p.w *= tanh_half_from_exp(e.w);
        }
    } else {
#pragma unroll
        for (int k = 0; k < 6; k++) {
            float4 s = *(const float4*)&g_st[idx[k] * NB + b];
            p.x *= s.x; p.y *= s.y; p.z *= s.z; p.w *= s.w;
        }
    }
    *(float4*)&g_P[c * NB + b] = p;
}

// ---------------------------------------------------------------- fused check-update(i) + var-update(i+1) + output(i)
// 4-wide over batch; FIRST/UPDATE compile-time -> lean per-variant code & regs.
template <int FIRST, int UPDATE>
__global__ void v_kernel(const int* __restrict__ chk, float* __restrict__ out, int iter) {
    __shared__ float tile[32][129];                // 32 v rows x 128 b cols (pad -> conflict-free col reads)
    int tx = threadIdx.x, ty = threadIdx.y;        // block (32,8)
    int b4 = blockIdx.x * 128 + tx * 4;            // grid.x = NB/128 = 4
    int v0 = blockIdx.y * 32;                      // grid.y = NV/32 = 256

#pragma unroll
    for (int s = 0; s < 4; s++) {
        int vl = s * 8 + ty;
        int v  = v0 + vl;
        int e0 = 3 * v;

        float4 lv = *(const float4*)&g_llrT[v * NB + b4];
        float l[4] = {lv.x, lv.y, lv.z, lv.w};

        float EL[4];
        if (FIRST || UPDATE) {
            float4 Ev = *(const float4*)&g_EL[v * NB + b4];
            EL[0] = Ev.x; EL[1] = Ev.y; EL[2] = Ev.z; EL[3] = Ev.w;
        }

        float st[3][4];
        if (FIRST) {
#pragma unroll
            for (int j = 0; j < 4; j++) {
                float t = tanh_half_from_exp(EL[j]);   // all 3 edges identical at iter 0
                st[0][j] = t; st[1][j] = t; st[2][j] = t;
            }
        } else {
#pragma unroll
            for (int k = 0; k < 3; k++) {
                float4 sv = *(const float4*)&g_st[(e0 + k) * NB + b4];
                st[k][0] = sv.x; st[k][1] = sv.y; st[k][2] = sv.z; st[k][3] = sv.w;
            }
        }

        int c0 = chk[e0 + 0], c1 = chk[e0 + 1], c2 = chk[e0 + 2];  // uniform per warp
        float4 pv0 = *(const float4*)&g_P[c0 * NB + b4];
        float4 pv1 = *(const float4*)&g_P[c1 * NB + b4];
        float4 pv2 = *(const float4*)&g_P[c2 * NB + b4];
        float p[3][4] = {{pv0.x, pv0.y, pv0.z, pv0.w},
                         {pv1.x, pv1.y, pv1.z, pv1.w},
                         {pv2.x, pv2.y, pv2.z, pv2.w}};

        float r[3][4];
#pragma unroll
        for (int j = 0; j < 4; j++) {
            // r_e = e^{ext_e} = (st+P)/(st-P); signs cancel, r >= 0.
            r[0][j] = clamp_r(__fdividef(st[0][j] + p[0][j], st[0][j] - p[0][j]));
            r[1][j] = clamp_r(__fdividef(st[1][j] + p[1][j], st[1][j] - p[1][j]));
            r[2][j] = clamp_r(__fdividef(st[2][j] + p[2][j], st[2][j] - p[2][j]));
            tile[vl][tx * 4 + j] = l[j] + __logf(r[0][j] * r[1][j] * r[2][j]);  // out
        }

        if (UPDATE) {
            // e^{msg_e} = e^llr * product of the OTHER two r's (no exp/log round-trip)
            float4 w0, w1, w2;
            w0.x = tanh_half_from_exp(EL[0] * (r[1][0] * r[2][0]));
            w0.y = tanh_half_from_exp(EL[1] * (r[1][1] * r[2][1]));
            w0.z = tanh_half_from_exp(EL[2] * (r[1][2] * r[2][2]));
            w0.w = tanh_half_from_exp(EL[3] * (r[1][3] * r[2][3]));
            *(float4*)&g_st[(e0 + 0) * NB + b4] = w0;
            w1.x = tanh_half_from_exp(EL[0] * (r[0][0] * r[2][0]));
            w1.y = tanh_half_from_exp(EL[1] * (r[0][1] * r[2][1]));
            w1.z = tanh_half_from_exp(EL[2] * (r[0][2] * r[2][2]));
            w1.w = tanh_half_from_exp(EL[3] * (r[0][3] * r[2][3]));
            *(float4*)&g_st[(e0 + 1) * NB + b4] = w1;
            w2.x = tanh_half_from_exp(EL[0] * (r[0][0] * r[1][0]));
            w2.y = tanh_half_from_exp(EL[1] * (r[0][1] * r[1][1]));
            w2.z = tanh_half_from_exp(EL[2] * (r[0][2] * r[1][2]));
            w2.w = tanh_half_from_exp(EL[3] * (r[0][3] * r[1][3]));
            *(float4*)&g_st[(e0 + 2) * NB + b4] = w2;
        }
    }
    __syncthreads();

    // coalesced transposed write: out[iter][b][v], 128B per warp-row
    int base = iter * (NB * NV) + v0 + tx;
#pragma unroll 4
    for (int r2 = ty; r2 < 128; r2 += 8) {
        int b = blockIdx.x * 128 + r2;
        out[base + b * NV] = tile[tx][r2];
    }
}

// ---------------------------------------------------------------- launch
extern "C" void kernel_launch(void* const* d_in, const int* in_sizes, int n_in,
                              void* d_out, int out_size) {
    const float* llr = (const float*)d_in[0];
    // d_in[1] = var_index: structured as repeat(arange(NV), 3) -> not needed
    const int* chk = (const int*)d_in[2];
    float* out = (float*)d_out;

    dim3 blk(32, 8);
    dim3 cg(4, NC / 8);
    dim3 vg(NB / 128, NV / 32);

    k_prep<<<dim3(NV / 32, NB / 32), blk>>>(llr);
    build_inv<<<(NE + 255) / 256, 256>>>(chk);

    c_kernel<1><<<cg, blk>>>();
    v_kernel<1, 1><<<vg, blk>>>(chk, out, 0);
    for (int i = 1; i < NITER - 1; i++) {
        c_kernel<0><<<cg, blk>>>();
        v_kernel<0, 1><<<vg, blk>>>(chk, out, i);
    }
    c_kernel<0><<<cg, blk>>>();
    v_kernel<0, 0><<<vg, blk>>>(chk, out, NITER - 1);
}

// round 10
// speedup vs baseline: 1.4710x; 1.1969x over previous
#include <cuda_runtime.h>

#define NV 8192
#define NC 4096
#define NB 512
#define NE 24576
#define NITER 5
#define EPSF 1e-12f
// clip = float(1 - 1e-7) = 1 - 2^-23.  Image of [-clip, clip] under (1+x)/(1-x):
#define RMAXF 16777215.0f      // = 2^24 - 1
#define RMINF 5.9604648e-8f    // = 1/(2^24 - 1) rounded

#define TPB 512                // threads per CTA (one CTA per batch element)
#define VPT (NV / TPB)         // 16 vars / thread
#define CPT (NC / TPB)         // 8 checks / thread
#define SMEM_BYTES ((NE + NC) * 4)   // st (96KB) + P (16KB) = 114688 B

// Graph structure (device globals: allocation-free per harness rules)
__device__ int   g_inv[NE];    // check -> 6 edge ids (atomic build order)
__device__ int   g_cnt[NC];    // build counters
__device__ uint4 g_inv8[NC];   // 6 sorted u16 edge ids per check, one LDG.128
__device__ uint2 g_chk4[NV];   // 3 u16 check ids per var, one LDG.64

// ---------------------------------------------------------------- index build
__global__ void zero_cnt() {
    int i = blockIdx.x * blockDim.x + threadIdx.x;
    if (i < NC) g_cnt[i] = 0;
}

__global__ void build_inv(const int* __restrict__ chk) {
    int e = blockIdx.x * blockDim.x + threadIdx.x;
    if (e < NE) {
        int c = chk[e];
        int s = atomicAdd(&g_cnt[c], 1);
        g_inv[c * 6 + s] = e;
    }
}

// sort each check's 6 edges ascending (deterministic product order matching
// segment ops) and pack to u16; pack per-var check ids. Race-free: runs after
// build_inv, before the only consumer.
__global__ void pack_idx(const int* __restrict__ chk) {
    int i = blockIdx.x * blockDim.x + threadIdx.x;
    if (i < NC) {
        int a[6];
#pragma unroll
        for (int k = 0; k < 6; k++) a[k] = g_inv[i * 6 + k];
#pragma unroll
        for (int x = 1; x < 6; x++)
#pragma unroll
            for (int j = x; j > 0; j--)
                if (a[j] < a[j - 1]) { int t = a[j]; a[j] = a[j - 1]; a[j - 1] = t; }
        uint4 w;
        w.x = (unsigned)a[0] | ((unsigned)a[1] << 16);
        w.y = (unsigned)a[2] | ((unsigned)a[3] << 16);
        w.z = (unsigned)a[4] | ((unsigned)a[5] << 16);
        w.w = 0;
        g_inv8[i] = w;
    }
    if (i < NV) {
        uint2 w;
        w.x = (unsigned)chk[3 * i] | ((unsigned)chk[3 * i + 1] << 16);
        w.y = (unsigned)chk[3 * i + 2];
        g_chk4[i] = w;
    }
}

// ---------------------------------------------------------------- helpers
__device__ __forceinline__ float tanh_half_from_exp(float el) {
    float t = __fdividef(el - 1.0f, el + 1.0f);
    return t + copysignf(EPSF, t);
}

__device__ __forceinline__ float clamp_r(float r) {
    return fminf(fmaxf(r, RMINF), RMAXF);
}

// ---------------------------------------------------------------- persistent per-batch decoder
// One CTA decodes one batch element entirely in shared memory:
//   s_st[e] : signed (|tanh(msg/2)|+eps) per edge  (96 KB)
//   s_P[c]  : signed product of a check's 6 st     (16 KB)
// __syncthreads() is the check/var barrier; 5 iterations, zero global round-trips
// for messages.
__global__ void __launch_bounds__(TPB, 2)
spa_kernel(const float* __restrict__ llr, float* __restrict__ out) {
    extern __shared__ float sm[];
    float* s_st = sm;            // NE floats
    float* s_P  = sm + NE;       // NC floats

    int tid = threadIdx.x;
    int b   = blockIdx.x;
    const float* llr_b = llr + b * NV;

    // iter-0 messages: msg = llr on all 3 edges of each var.
    // stride-3 word stores -> conflict-free (gcd(3,32)=1).
#pragma unroll 2
    for (int m = 0; m < VPT; m++) {
        int v = tid + m * TPB;
        float el = __expf(llr_b[v]);
        float t  = tanh_half_from_exp(el);
        s_st[3 * v + 0] = t;
        s_st[3 * v + 1] = t;
        s_st[3 * v + 2] = t;
    }
    __syncthreads();

    for (int it = 0; it < NITER; it++) {
        // ---- check phase: P[c] = signed product of 6 st (ascending edge order)
#pragma unroll 2
        for (int m = 0; m < CPT; m++) {
            int c = tid + m * TPB;
            uint4 w = g_inv8[c];
            float p = s_st[w.x & 0xFFFF];
            p *= s_st[w.x >> 16];
            p *= s_st[w.y & 0xFFFF];
            p *= s_st[w.y >> 16];
            p *= s_st[w.z & 0xFFFF];
            p *= s_st[w.z >> 16];
            s_P[c] = p;
        }
        __syncthreads();

        // ---- var phase: out(it) + next-iteration st
        int outbase = it * (NB * NV) + b * NV;
#pragma unroll 2
        for (int m = 0; m < VPT; m++) {
            int v  = tid + m * TPB;
            int e0 = 3 * v;
            float st0 = s_st[e0 + 0];
            float st1 = s_st[e0 + 1];
            float st2 = s_st[e0 + 2];
            uint2 cw = g_chk4[v];
            float p0 = s_P[cw.x & 0xFFFF];
            float p1 = s_P[cw.x >> 16];
            float p2 = s_P[cw.y];

            // r_e = e^{ext_e} = (st+P)/(st-P); signs cancel, r >= 0;
            // clamp is the exact image of the reference's loo clip.
            float r0 = clamp_r(__fdividef(st0 + p0, st0 - p0));
            float r1 = clamp_r(__fdividef(st1 + p1, st1 - p1));
            float r2 = clamp_r(__fdividef(st2 + p2, st2 - p2));

            float l = llr_b[v];
            out[outbase + v] = l + __logf(r0 * r1 * r2);   // llr + sum of ext

            if (it < NITER - 1) {
                // e^{msg_e} = e^llr * product of the OTHER two r's
                float el = __expf(l);
                s_st[e0 + 0] = tanh_half_from_exp(el * (r1 * r2));
                s_st[e0 + 1] = tanh_half_from_exp(el * (r0 * r2));
                s_st[e0 + 2] = tanh_half_from_exp(el * (r0 * r1));
            }
        }
        __syncthreads();
    }
}

// ---------------------------------------------------------------- launch
extern "C" void kernel_launch(void* const* d_in, const int* in_sizes, int n_in,
                              void* d_out, int out_size) {
    const float* llr = (const float*)d_in[0];
    // d_in[1] = var_index: structured as repeat(arange(NV), 3) -> not needed
    const int* chk = (const int*)d_in[2];
    float* out = (float*)d_out;

    cudaFuncSetAttribute(spa_kernel, cudaFuncAttributeMaxDynamicSharedMemorySize,
                         SMEM_BYTES);

    zero_cnt<<<(NC + 255) / 256, 256>>>();
    build_inv<<<(NE + 255) / 256, 256>>>(chk);
    pack_idx<<<(NV + 255) / 256, 256>>>(chk);
    spa_kernel<<<NB, TPB, SMEM_BYTES>>>(llr, out);
}

// round 11
// speedup vs baseline: 1.7977x; 1.2221x over previous
#include <cuda_runtime.h>

#define NV 8192
#define NC 4096
#define NB 512
#define NE 24576
#define NITER 5
#define EPSF 1e-12f
// clip = float(1 - 1e-7) = 1 - 2^-23.  Image of [-clip, clip] under (1+x)/(1-x):
#define RMAXF 16777215.0f      // = 2^24 - 1
#define RMINF 5.9604648e-8f    // = 1/(2^24 - 1) rounded

#define TPB 1024               // threads per CTA; one CTA = TWO batch elements (float2)
#define VPT (NV / TPB)         // 8 vars / thread
#define CPT (NC / TPB)         // 4 checks / thread
// smem: st planes float2[3][NV] (192KB) + P float2[NC] (32KB) = 229376 B (opt-in)
#define SMEM_BYTES ((3 * NV + NC) * 8)

// Graph structure (device globals: allocation-free per harness rules)
__device__ int   g_inv[NE];    // check -> 6 edge ids (atomic build order)
__device__ int   g_cnt[NC];    // build counters
__device__ uint4 g_inv8[NC];   // 6 u16 slotted-st offsets per check (edge-ascending order)
__device__ uint2 g_chk4[NV];   // 3 u16 check ids per var

// ---------------------------------------------------------------- index build
__global__ void zero_cnt() {
    int i = blockIdx.x * blockDim.x + threadIdx.x;
    if (i < NC) g_cnt[i] = 0;
}

__global__ void build_inv(const int* __restrict__ chk) {
    int e = blockIdx.x * blockDim.x + threadIdx.x;
    if (e < NE) {
        int c = chk[e];
        int s = atomicAdd(&g_cnt[c], 1);
        g_inv[c * 6 + s] = e;
    }
}

// Sort each check's 6 edges ascending (deterministic product order), then map
// edge id -> slotted-layout offset: off(e) = (e%3)*NV + e/3. Pack to u16.
__global__ void pack_idx(const int* __restrict__ chk) {
    int i = blockIdx.x * blockDim.x + threadIdx.x;
    if (i < NC) {
        int a[6];
#pragma unroll
        for (int k = 0; k < 6; k++) a[k] = g_inv[i * 6 + k];
#pragma unroll
        for (int x = 1; x < 6; x++)
#pragma unroll
            for (int j = x; j > 0; j--)
                if (a[j] < a[j - 1]) { int t = a[j]; a[j] = a[j - 1]; a[j - 1] = t; }
        unsigned o[6];
#pragma unroll
        for (int k = 0; k < 6; k++) {
            int e = a[k];
            o[k] = (unsigned)((e % 3) * NV + (e / 3));
        }
        uint4 w;
        w.x = o[0] | (o[1] << 16);
        w.y = o[2] | (o[3] << 16);
        w.z = o[4] | (o[5] << 16);
        w.w = 0;
        g_inv8[i] = w;
    }
    if (i < NV) {
        uint2 w;
        w.x = (unsigned)chk[3 * i] | ((unsigned)chk[3 * i + 1] << 16);
        w.y = (unsigned)chk[3 * i + 2];
        g_chk4[i] = w;
    }
}

// ---------------------------------------------------------------- helpers
__device__ __forceinline__ float tanh_half_from_exp(float el) {
    float t = __fdividef(el - 1.0f, el + 1.0f);
    return t + copysignf(EPSF, t);
}

__device__ __forceinline__ float clamp_r(float r) {
    return fminf(fmaxf(r, RMINF), RMAXF);
}

__device__ __forceinline__ float2 r_pair(float2 st, float2 p) {
    float2 r;
    r.x = clamp_r(__fdividef(st.x + p.x, st.x - p.x));
    r.y = clamp_r(__fdividef(st.y + p.y, st.y - p.y));
    return r;
}

// ---------------------------------------------------------------- persistent per-batch-pair decoder
// One CTA decodes TWO batch elements entirely in shared memory (float2 lanes):
//   s_st[3*NV] : slotted st planes — var v's edges at {v, NV+v, 2NV+v}
//   s_P[NC]    : per-check signed product of 6 st
// Every random crossbar access serves both batches at once.
__global__ void __launch_bounds__(TPB, 1)
spa_kernel(const float* __restrict__ llr, float* __restrict__ out) {
    extern __shared__ float2 sm[];
    float2* s_st = sm;            // 3*NV float2
    float2* s_P  = sm + 3 * NV;   // NC float2

    int tid = threadIdx.x;
    int b0  = 2 * blockIdx.x;
    const float* llr0 = llr + (b0 + 0) * NV;
    const float* llr1 = llr + (b0 + 1) * NV;

    // iter-0 messages: msg = llr on all 3 edges of each var (contiguous float2 stores)
#pragma unroll
    for (int m = 0; m < VPT; m++) {
        int v = tid + m * TPB;
        float2 t;
        t.x = tanh_half_from_exp(__expf(llr0[v]));
        t.y = tanh_half_from_exp(__expf(llr1[v]));
        s_st[v]          = t;
        s_st[NV + v]     = t;
        s_st[2 * NV + v] = t;
    }
    __syncthreads();

    for (int it = 0; it < NITER; it++) {
        // ---- check phase: P[c] = signed product of 6 st (ascending edge order)
#pragma unroll
        for (int m = 0; m < CPT; m++) {
            int c = tid + m * TPB;
            uint4 w = g_inv8[c];
            float2 a0 = s_st[w.x & 0xFFFF];
            float2 a1 = s_st[w.x >> 16];
            float2 a2 = s_st[w.y & 0xFFFF];
            float2 a3 = s_st[w.y >> 16];
            float2 a4 = s_st[w.z & 0xFFFF];
            float2 a5 = s_st[w.z >> 16];
            float2 p;
            p.x = ((((a0.x * a1.x) * a2.x) * a3.x) * a4.x) * a5.x;
            p.y = ((((a0.y * a1.y) * a2.y) * a3.y) * a4.y) * a5.y;
            s_P[c] = p;
        }
        __syncthreads();

        // ---- var phase: out(it) + next-iteration st
        int ob0 = it * (NB * NV) + (b0 + 0) * NV;
        int ob1 = it * (NB * NV) + (b0 + 1) * NV;
#pragma unroll
        for (int m = 0; m < VPT; m++) {
            int v = tid + m * TPB;
            float2 st0 = s_st[v];
            float2 st1 = s_st[NV + v];
            float2 st2 = s_st[2 * NV + v];
            uint2 cw = g_chk4[v];
            float2 p0 = s_P[cw.x & 0xFFFF];
            float2 p1 = s_P[cw.x >> 16];
            float2 p2 = s_P[cw.y];

            // r_e = e^{ext_e} = (st+P)/(st-P); signs cancel, r >= 0;
            // clamp is the exact image of the reference's loo clip.
            float2 r0 = r_pair(st0, p0);
            float2 r1 = r_pair(st1, p1);
            float2 r2 = r_pair(st2, p2);

            float l0 = llr0[v], l1 = llr1[v];
            out[ob0 + v] = l0 + __logf(r0.x * r1.x * r2.x);  // llr + sum of ext
            out[ob1 + v] = l1 + __logf(r0.y * r1.y * r2.y);

            if (it < NITER - 1) {
                // e^{msg_e} = e^llr * product of the OTHER two r's
                float e0 = __expf(l0), e1 = __expf(l1);
                float2 w0, w1, w2;
                w0.x = tanh_half_from_exp(e0 * (r1.x * r2.x));
                w0.y = tanh_half_from_exp(e1 * (r1.y * r2.y));
                w1.x = tanh_half_from_exp(e0 * (r0.x * r2.x));
                w1.y = tanh_half_from_exp(e1 * (r0.y * r2.y));
                w2.x = tanh_half_from_exp(e0 * (r0.x * r1.x));
                w2.y = tanh_half_from_exp(e1 * (r0.y * r1.y));
                s_st[v]          = w0;
                s_st[NV + v]     = w1;
                s_st[2 * NV + v] = w2;
            }
        }
        __syncthreads();
    }
}

// ---------------------------------------------------------------- launch
extern "C" void kernel_launch(void* const* d_in, const int* in_sizes, int n_in,
                              void* d_out, int out_size) {
    const float* llr = (const float*)d_in[0];
    // d_in[1] = var_index: structured as repeat(arange(NV), 3) -> not needed
    const int* chk = (const int*)d_in[2];
    float* out = (float*)d_out;

    cudaFuncSetAttribute(spa_kernel, cudaFuncAttributeMaxDynamicSharedMemorySize,
                         SMEM_BYTES);

    zero_cnt<<<(NC + 255) / 256, 256>>>();
    build_inv<<<(NE + 255) / 256, 256>>>(chk);
    pack_idx<<<(NV + 255) / 256, 256>>>(chk);
    spa_kernel<<<NB / 2, TPB, SMEM_BYTES>>>(llr, out);
}